// round 12
// baseline (speedup 1.0000x reference)
#include <cuda_runtime.h>
#include <cuda_fp16.h>
#include <math.h>

#define Bdim 128
#define Ldim 256
#define Hdim 512
#define H3   1536
#define OUTD 256
#define BL   (Bdim*Ldim)   // 32768
#define NBLK 128

// ---------------- scratch (device globals) ----------------------------------
__device__ float g_xmean[Bdim*Hdim];
__device__ float g_delta[BL*Hdim];
__device__ float g_xhat [BL*Hdim];
__device__ __align__(16) __half g_gammah[BL*Hdim];     // fp16 gamma_h
__device__ float g_pre  [BL*H3];
__device__ float g_hseq [BL*Hdim];
__device__ float g_h    [Bdim*Hdim];
__device__ float g_z    [Bdim*Hdim];
__device__ __align__(16) __half g_rh[Bdim*Hdim];       // fp16 r*gamma*h
__device__ unsigned g_arr4[4*32];
__device__ volatile unsigned g_rel4[4*32];

// ---------------- per-row-group barrier (32 blocks) -------------------------
__device__ __forceinline__ void groupbar(int rg) {
    __syncthreads();
    if (threadIdx.x == 0) {
        __threadfence();
        unsigned gen = g_rel4[rg * 32];
        if (atomicInc((unsigned*)&g_arr4[rg * 32], 31u) == 31u) {
            __threadfence();
            g_rel4[rg * 32] = gen + 1u;
        } else {
            while (g_rel4[rg * 32] == gen) { __nanosleep(4); }
        }
    }
    __syncthreads();
}

__device__ __forceinline__ float sigmoidf_(float x) { return 1.f / (1.f + expf(-x)); }

__device__ __forceinline__ void mma_f16(float* c, const unsigned* a, const unsigned* b) {
    asm volatile("mma.sync.aligned.m16n8k16.row.col.f32.f16.f16.f32 "
        "{%0,%1,%2,%3}, {%4,%5,%6,%7}, {%8,%9}, {%0,%1,%2,%3};"
        : "+f"(c[0]), "+f"(c[1]), "+f"(c[2]), "+f"(c[3])
        : "r"(a[0]), "r"(a[1]), "r"(a[2]), "r"(a[3]), "r"(b[0]), "r"(b[1]));
}
__device__ __forceinline__ unsigned pack_h2(float a, float b) {
    __half2 h = __floats2half2_rn(a, b);
    return *(unsigned*)&h;
}
__device__ __forceinline__ float2 h2f2(unsigned u) {
    __half2 h = *(__half2*)&u;
    return __half22float2(h);
}
__device__ __forceinline__ uint4 pack8(float4 a, float4 b) {
    uint4 r;
    r.x = pack_h2(a.x, a.y); r.y = pack_h2(a.z, a.w);
    r.z = pack_h2(b.x, b.y); r.w = pack_h2(b.z, b.w);
    return r;
}
__device__ __forceinline__ uint4 packB(float4 lo, float4 hi) {
    uint4 r;
    r.x = pack_h2(lo.x, hi.x); r.y = pack_h2(lo.y, hi.y);
    r.z = pack_h2(lo.z, hi.z); r.w = pack_h2(lo.w, hi.w);
    return r;
}

// ---------------- K1: x_mean -------------------------------------------------
__global__ void __launch_bounds__(256) k_xmean(const float* __restrict__ C,
                                               const int* __restrict__ mask) {
    int idx = blockIdx.x * 256 + threadIdx.x;
    int b = idx >> 9, h = idx & 511;
    const int* mp = mask + (size_t)b * Ldim * Hdim + h;
    float s = 0.f, cnt = 0.f;
    #pragma unroll 4
    for (int l = 0; l < Ldim; l++) {
        float m = (float)mp[l * Hdim];
        s   += m * C[l * Hdim + h];
        cnt += m;
    }
    g_xmean[idx] = s / fmaxf(cnt, 1.f);
}

// ---------------- K2: elementwise scans --------------------------------------
__global__ void __launch_bounds__(256) k_scan(const float* __restrict__ C,
                                              const float* __restrict__ t,
                                              const int* __restrict__ mask,
                                              const float* __restrict__ w_gx,
                                              const float* __restrict__ b_gx) {
    int idx = blockIdx.x * 256 + threadIdx.x;
    int b = idx >> 9, h = idx & 511;
    float xm = g_xmean[idx];
    float xl = xm, dprev = 0.f, mprev = 1.f, tprev = 0.f;
    float wg = w_gx[h], bg = b_gx[h];
    const int* mp = mask + (size_t)b * Ldim * Hdim + h;
    const float* tp = t + b * Ldim;
    for (int l = 0; l < Ldim; l++) {
        float tc = tp[l];
        float dt = (l == 0) ? 0.f : (tc - tprev);
        tprev = tc;
        float m = (float)mp[l * Hdim];
        float delta = dt + (1.f - mprev) * dprev;
        float gx = expf(-fmaxf(0.f, wg * delta + bg));
        float x  = C[(l << 9) + h];
        int gi = ((b * Ldim + l) << 9) + h;
        g_delta[gi] = delta;
        g_xhat[gi]  = m * x + (1.f - m) * (gx * xl + (1.f - gx) * xm);
        xl = m * x + (1.f - m) * xl;
        dprev = delta; mprev = m;
    }
}

// =============================================================================
// fp16 m16n8k16 phase-A GEMMs, BK=32 double-buffered stages.
// A smem [128][20] half2 words (16 kpairs + pad 4), B smem [16][136].
// =============================================================================
#define ASW 20
#define BSW 136
#define AHW (128*ASW)    // 2560 words
#define BHW (16*BSW)     // 2176 words

// A-loader: arow = tid&127, K half-slab kh16 = (tid>>7)*16, word kw8 = (tid>>7)*8
#define LOAD_A_F32(src, K, k0)                                                 \
    av0 = *(const float4*)&(src)[(size_t)(bm + arow) * (K) + (k0) + kh16];     \
    av1 = *(const float4*)&(src)[(size_t)(bm + arow) * (K) + (k0) + kh16 + 4]; \
    av2 = *(const float4*)&(src)[(size_t)(bm + arow) * (K) + (k0) + kh16 + 8]; \
    av3 = *(const float4*)&(src)[(size_t)(bm + arow) * (K) + (k0) + kh16 + 12];
#define STORE_A(buf)                                                           \
    *(uint4*)&Ah[buf][arow * ASW + kw8]     = pack8(av0, av1);                 \
    *(uint4*)&Ah[buf][arow * ASW + kw8 + 4] = pack8(av2, av3);
// B-loader: kpb = tid>>5 (0..7), nc4 = lane*4; loads kpair rows kpb & kpb+8
#define LOAD_B(src, N, k0)                                                     \
    bv0 = *(const float4*)&(src)[(size_t)((k0) + 2 * kpb) * (N) + bn + nc4];   \
    bv1 = *(const float4*)&(src)[(size_t)((k0) + 2 * kpb + 1) * (N) + bn + nc4];\
    bv2 = *(const float4*)&(src)[(size_t)((k0) + 2 * kpb + 16) * (N) + bn + nc4];\
    bv3 = *(const float4*)&(src)[(size_t)((k0) + 2 * kpb + 17) * (N) + bn + nc4];
#define STORE_B(buf)                                                           \
    *(uint4*)&Bh[buf][kpb * BSW + nc4]       = packB(bv0, bv1);                \
    *(uint4*)&Bh[buf][(kpb + 8) * BSW + nc4] = packB(bv2, bv3);

#define MMA_STAGE(buf)                                                         \
    {                                                                          \
        const unsigned* A = Ah[buf];                                           \
        const unsigned* B = Bh[buf];                                           \
        _Pragma("unroll")                                                      \
        for (int s = 0; s < 2; s++) {                                          \
            unsigned af[4][4], bf[4][2];                                       \
            _Pragma("unroll")                                                  \
            for (int mt = 0; mt < 4; mt++) {                                   \
                int mb = wm + mt * 16;                                         \
                af[mt][0] = A[(mb + g) * ASW + s * 8 + tg];                    \
                af[mt][1] = A[(mb + g + 8) * ASW + s * 8 + tg];                \
                af[mt][2] = A[(mb + g) * ASW + s * 8 + tg + 4];                \
                af[mt][3] = A[(mb + g + 8) * ASW + s * 8 + tg + 4];            \
            }                                                                  \
            _Pragma("unroll")                                                  \
            for (int nt = 0; nt < 4; nt++) {                                   \
                int nb = wn + nt * 8;                                          \
                bf[nt][0] = B[(s * 8 + tg) * BSW + nb + g];                    \
                bf[nt][1] = B[(s * 8 + tg + 4) * BSW + nb + g];                \
            }                                                                  \
            _Pragma("unroll")                                                  \
            for (int mt = 0; mt < 4; mt++)                                     \
                _Pragma("unroll")                                              \
                for (int nt = 0; nt < 4; nt++)                                 \
                    mma_f16(acc[mt][nt], af[mt], bf[nt]);                      \
        }                                                                      \
    }

#define GEMM_DECLS                                                             \
    const int tid = threadIdx.x;                                               \
    const int bn = blockIdx.x * 128, bm = blockIdx.y * 128;                    \
    const int wid = tid >> 5, lane = tid & 31;                                 \
    const int wm = (wid >> 2) * 64, wn = (wid & 3) * 32;                       \
    const int g = lane >> 2, tg = lane & 3;                                    \
    const int arow = tid & 127, kh16 = (tid >> 7) * 16, kw8 = (tid >> 7) * 8;  \
    const int kpb = tid >> 5, nc4 = lane * 4;                                  \
    float acc[4][4][4];                                                        \
    _Pragma("unroll")                                                          \
    for (int i = 0; i < 4; i++)                                                \
        _Pragma("unroll")                                                      \
        for (int j = 0; j < 4; j++)                                            \
            _Pragma("unroll")                                                  \
            for (int q = 0; q < 4; q++) acc[i][j][q] = 0.f;                    \
    float4 av0, av1, av2, av3, bv0, bv1, bv2, bv3;

// ---------------- K3: gamma_h = exp(-relu(delta @ W_gh + b_gh)) -> fp16 ------
__global__ void __launch_bounds__(256, 2) k_gh_mma(const float* __restrict__ Bw,
                                                   const float* __restrict__ bias) {
    __shared__ __align__(16) unsigned Ah[2][AHW];
    __shared__ __align__(16) unsigned Bh[2][BHW];
    GEMM_DECLS
    LOAD_A_F32(g_delta, Hdim, 0) LOAD_B(Bw, Hdim, 0)
    STORE_A(0) STORE_B(0)
    __syncthreads();
    const int KT = Hdim / 32;   // 16
    for (int kt = 0; kt < KT; kt++) {
        if (kt + 1 < KT) {
            int k0 = (kt + 1) * 32;
            LOAD_A_F32(g_delta, Hdim, k0) LOAD_B(Bw, Hdim, k0)
        }
        MMA_STAGE(kt & 1)
        if (kt + 1 < KT) { STORE_A((kt + 1) & 1) STORE_B((kt + 1) & 1) }
        __syncthreads();
    }
    #pragma unroll
    for (int mt = 0; mt < 4; mt++) {
        #pragma unroll
        for (int nt = 0; nt < 4; nt++) {
            int col = bn + wn + nt * 8 + tg * 2;
            float b0 = bias[col], b1 = bias[col + 1];
            int r0 = bm + wm + mt * 16 + g;
            float e00 = expf(-fmaxf(0.f, acc[mt][nt][0] + b0));
            float e01 = expf(-fmaxf(0.f, acc[mt][nt][1] + b1));
            float e10 = expf(-fmaxf(0.f, acc[mt][nt][2] + b0));
            float e11 = expf(-fmaxf(0.f, acc[mt][nt][3] + b1));
            *(unsigned*)&g_gammah[(size_t)r0 * Hdim + col] = pack_h2(e00, e01);
            *(unsigned*)&g_gammah[(size_t)(r0 + 8) * Hdim + col] = pack_h2(e10, e11);
        }
    }
}

// ---------------- K4: pre = x_hat@Wx + m@Wm + b (K virtualized 1024) ---------
__global__ void __launch_bounds__(256, 2) k_pre_mma(const int* __restrict__ mask,
                                                    const float* __restrict__ Wx,
                                                    const float* __restrict__ Wm,
                                                    const float* __restrict__ bias) {
    __shared__ __align__(16) unsigned Ah[2][AHW];
    __shared__ __align__(16) unsigned Bh[2][BHW];
    GEMM_DECLS
    LOAD_A_F32(g_xhat, Hdim, 0) LOAD_B(Wx, H3, 0)
    STORE_A(0) STORE_B(0)
    __syncthreads();
    const int KT = 32;   // 2 passes x 16
    for (int kt = 0; kt < KT; kt++) {
        if (kt + 1 < KT) {
            int nkt = kt + 1;
            int k0 = (nkt & 15) * 32;
            if (nkt < 16) {
                LOAD_A_F32(g_xhat, Hdim, k0) LOAD_B(Wx, H3, k0)
            } else {
                int4 m0 = *(const int4*)&mask[(size_t)(bm + arow) * Hdim + k0 + kh16];
                int4 m1 = *(const int4*)&mask[(size_t)(bm + arow) * Hdim + k0 + kh16 + 4];
                int4 m2 = *(const int4*)&mask[(size_t)(bm + arow) * Hdim + k0 + kh16 + 8];
                int4 m3 = *(const int4*)&mask[(size_t)(bm + arow) * Hdim + k0 + kh16 + 12];
                av0 = make_float4((float)m0.x, (float)m0.y, (float)m0.z, (float)m0.w);
                av1 = make_float4((float)m1.x, (float)m1.y, (float)m1.z, (float)m1.w);
                av2 = make_float4((float)m2.x, (float)m2.y, (float)m2.z, (float)m2.w);
                av3 = make_float4((float)m3.x, (float)m3.y, (float)m3.z, (float)m3.w);
                LOAD_B(Wm, H3, k0)
            }
        }
        MMA_STAGE(kt & 1)
        if (kt + 1 < KT) { STORE_A((kt + 1) & 1) STORE_B((kt + 1) & 1) }
        __syncthreads();
    }
    #pragma unroll
    for (int mt = 0; mt < 4; mt++) {
        #pragma unroll
        for (int nt = 0; nt < 4; nt++) {
            int col = bn + wn + nt * 8 + tg * 2;
            float b0 = bias[col], b1 = bias[col + 1];
            int r0 = bm + wm + mt * 16 + g;
            float2 o0, o1;
            o0.x = acc[mt][nt][0] + b0; o0.y = acc[mt][nt][1] + b1;
            o1.x = acc[mt][nt][2] + b0; o1.y = acc[mt][nt][3] + b1;
            *(float2*)&g_pre[(size_t)r0 * H3 + col] = o0;
            *(float2*)&g_pre[(size_t)(r0 + 8) * H3 + col] = o1;
        }
    }
}

// ---------------- K6: out = h_seq @ W_out + b_out ----------------------------
__global__ void __launch_bounds__(256, 2) k_out_mma(const float* __restrict__ Bw,
                                                    const float* __restrict__ bias,
                                                    float* __restrict__ out) {
    __shared__ __align__(16) unsigned Ah[2][AHW];
    __shared__ __align__(16) unsigned Bh[2][BHW];
    GEMM_DECLS
    LOAD_A_F32(g_hseq, Hdim, 0) LOAD_B(Bw, OUTD, 0)
    STORE_A(0) STORE_B(0)
    __syncthreads();
    const int KT = Hdim / 32;
    for (int kt = 0; kt < KT; kt++) {
        if (kt + 1 < KT) {
            int k0 = (kt + 1) * 32;
            LOAD_A_F32(g_hseq, Hdim, k0) LOAD_B(Bw, OUTD, k0)
        }
        MMA_STAGE(kt & 1)
        if (kt + 1 < KT) { STORE_A((kt + 1) & 1) STORE_B((kt + 1) & 1) }
        __syncthreads();
    }
    #pragma unroll
    for (int mt = 0; mt < 4; mt++) {
        #pragma unroll
        for (int nt = 0; nt < 4; nt++) {
            int col = bn + wn + nt * 8 + tg * 2;
            float b0 = bias[col], b1 = bias[col + 1];
            int r0 = bm + wm + mt * 16 + g;
            float2 o0, o1;
            o0.x = acc[mt][nt][0] + b0; o0.y = acc[mt][nt][1] + b1;
            o1.x = acc[mt][nt][2] + b0; o1.y = acc[mt][nt][3] + b1;
            *(float2*)&out[(size_t)r0 * OUTD + col] = o0;
            *(float2*)&out[(size_t)(r0 + 8) * OUTD + col] = o1;
        }
    }
}

// =============================================================================
// K5: persistent sequential recurrence — unchanged from R10 (fp16 data plane).
// =============================================================================
#define OFF_WH1 0
#define WS1H    40
#define OFF_WH3 10240
#define WS3H    24
#define OFF_AB  16384
#define ASH     260
#define OFF_RED 24704
#define RSTR1   36
#define RKG1    (32*RSTR1)
#define RSTR2   20
#define RKG2    (32*RSTR2)
#define SMEM_SEQ ((OFF_RED + 8*RKG1) * 4)   // 135680 B

__global__ void __launch_bounds__(256, 1) k_seq(const float* __restrict__ Wh) {
    extern __shared__ unsigned smu[];
    unsigned* Wh1h = smu + OFF_WH1;
    unsigned* Wh3h = smu + OFF_WH3;
    unsigned* Abh  = smu + OFF_AB;
    float*    Red  = (float*)(smu + OFF_RED);

    const int tid = threadIdx.x;
    const int blk = blockIdx.x;
    const int rg  = blk >> 5;
    const int tn  = blk & 31;
    const int m0  = rg * 32;
    const int n0  = tn * 32;
    const int n02 = tn * 16;

    for (int i = tid; i < 256 * 32; i += 256) {
        int kp = i >> 5, n = i & 31;
        float lo = Wh[(size_t)(2 * kp) * H3 + n0 + n];
        float hi = Wh[(size_t)(2 * kp + 1) * H3 + n0 + n];
        Wh1h[kp * WS1H + n] = pack_h2(lo, hi);
    }
    for (int i = tid; i < 256 * 16; i += 256) {
        int kp = i >> 4, n = i & 15;
        float lo = Wh[(size_t)(2 * kp) * H3 + 1024 + n02 + n];
        float hi = Wh[(size_t)(2 * kp + 1) * H3 + 1024 + n02 + n];
        Wh3h[kp * WS3H + n] = pack_h2(lo, hi);
    }
    if (tn == 0)
        for (int i = tid; i < 32 * 512; i += 256) g_h[m0 * 512 + i] = 0.f;
    groupbar(rg);

    const int lane = tid & 31, kg = tid >> 5;
    const int g = lane >> 2, tg = lane & 3;
    const int kpbase = (kg * 64) >> 1;
    const int pr = tid >> 3, pc = (tid & 7) * 4;
    const int pw = (tid & 7) * 4;
    const int rr1 = tid >> 3, cc1 = (tid * 4) & 31;
    const int rr2 = tid >> 3, cc2 = (tid * 2) & 15;
    const int nn1 = (n0 >= 512 ? n0 - 512 : 0) + cc1;

    for (int step = 0; step < Ldim; step++) {
        float4 pf_pre4 = __ldcg((const float4*)&g_pre[(size_t)((m0 + rr1) * Ldim + step) * H3 + n0 + cc1]);
        float2 pf_pre2 = __ldcg((const float2*)&g_pre[(size_t)((m0 + rr2) * Ldim + step) * H3 + 1024 + n02 + cc2]);
        unsigned pf_gm2u = *(const unsigned*)&g_gammah[(size_t)((m0 + rr2) * Ldim + step) * 512 + n02 + cc2];
        float2 pf_h2   = __ldcg((const float2*)&g_h[(m0 + rr2) * 512 + n02 + cc2]);
        uint2  pf_gm1u = *(const uint2*)&g_gammah[(size_t)((m0 + rr1) * Ldim + step) * 512 + nn1];
        float4 pf_h1   = __ldcg((const float4*)&g_h[(m0 + rr1) * 512 + nn1]);

        {
            const float* hrow = g_h + (m0 + pr) * 512;
            const __half* grow = g_gammah + (size_t)((m0 + pr) * Ldim + step) * 512;
            #pragma unroll
            for (int j = 0; j < 16; j++) {
                int k = pc + 32 * j;
                float4 h4 = __ldcg((const float4*)(hrow + k));
                uint2 gp = *(const uint2*)(grow + k);
                float2 f01 = h2f2(gp.x), f23 = h2f2(gp.y);
                unsigned o0 = pack_h2(h4.x * f01.x, h4.y * f01.y);
                unsigned o1 = pack_h2(h4.z * f23.x, h4.w * f23.y);
                *(uint2*)&Abh[pr * ASH + (k >> 1)] = make_uint2(o0, o1);
            }
        }
        __syncthreads();
        {
            float acc[2][4][4];
            #pragma unroll
            for (int mt = 0; mt < 2; mt++)
                #pragma unroll
                for (int nt = 0; nt < 4; nt++)
                    #pragma unroll
                    for (int q = 0; q < 4; q++) acc[mt][nt][q] = 0.f;
            #pragma unroll
            for (int ks = 0; ks < 4; ks++) {
                int kp0 = kpbase + ks * 8;
                unsigned af[2][4];
                #pragma unroll
                for (int mt = 0; mt < 2; mt++) {
                    int mb = mt * 16;
                    af[mt][0] = Abh[(mb + g) * ASH + kp0 + tg];
                    af[mt][1] = Abh[(mb + g + 8) * ASH + kp0 + tg];
                    af[mt][2] = Abh[(mb + g) * ASH + kp0 + tg + 4];
                    af[mt][3] = Abh[(mb + g + 8) * ASH + kp0 + tg + 4];
                }
                unsigned bf[4][2];
                #pragma unroll
                for (int nt = 0; nt < 4; nt++) {
                    bf[nt][0] = Wh1h[(kp0 + tg) * WS1H + nt * 8 + g];
                    bf[nt][1] = Wh1h[(kp0 + tg + 4) * WS1H + nt * 8 + g];
                }
                #pragma unroll
                for (int mt = 0; mt < 2; mt++)
                    #pragma unroll
                    for (int nt = 0; nt < 4; nt++)
                        mma_f16(acc[mt][nt], af[mt], bf[nt]);
            }
            #pragma unroll
            for (int mt = 0; mt < 2; mt++)
                #pragma unroll
                for (int nt = 0; nt < 4; nt++) {
                    float* base = &Red[kg * RKG1 + (mt * 16 + g) * RSTR1 + nt * 8 + tg * 2];
                    *(float2*)base = make_float2(acc[mt][nt][0], acc[mt][nt][1]);
                    *(float2*)(base + 8 * RSTR1) = make_float2(acc[mt][nt][2], acc[mt][nt][3]);
                }
        }
        __syncthreads();
        {
            float4 s = *(float4*)&Red[rr1 * RSTR1 + cc1];
            #pragma unroll
            for (int q = 1; q < 8; q++) {
                float4 v = *(float4*)&Red[q * RKG1 + rr1 * RSTR1 + cc1];
                s.x += v.x; s.y += v.y; s.z += v.z; s.w += v.w;
            }
            int b = m0 + rr1;
            float s0 = sigmoidf_(s.x + pf_pre4.x);
            float s1 = sigmoidf_(s.y + pf_pre4.y);
            float s2 = sigmoidf_(s.z + pf_pre4.z);
            float s3 = sigmoidf_(s.w + pf_pre4.w);
            if (n0 < 512) {
                *(float4*)&g_z[b * 512 + n0 + cc1] = make_float4(s0, s1, s2, s3);
            } else {
                float2 ga = h2f2(pf_gm1u.x), gb = h2f2(pf_gm1u.y);
                unsigned r01 = pack_h2(s0 * ga.x * pf_h1.x, s1 * ga.y * pf_h1.y);
                unsigned r23 = pack_h2(s2 * gb.x * pf_h1.z, s3 * gb.y * pf_h1.w);
                *(uint2*)&g_rh[b * 512 + nn1] = make_uint2(r01, r23);
            }
        }
        groupbar(rg);

        float2 pf_z2 = __ldcg((const float2*)&g_z[(m0 + rr2) * 512 + n02 + cc2]);

        {
            const unsigned* rrow = (const unsigned*)(g_rh + (m0 + pr) * 512);
            #pragma unroll
            for (int j = 0; j < 8; j++) {
                int w = pw + 32 * j;
                *(uint4*)&Abh[pr * ASH + w] = __ldcg((const uint4*)(rrow + w));
            }
        }
        __syncthreads();
        {
            float acc[2][2][4];
            #pragma unroll
            for (int mt = 0; mt < 2; mt++)
                #pragma unroll
                for (int nt = 0; nt < 2; nt++)
                    #pragma unroll
                    for (int q = 0; q < 4; q++) acc[mt][nt][q] = 0.f;
            #pragma unroll
            for (int ks = 0; ks < 4; ks++) {
                int kp0 = kpbase + ks * 8;
                unsigned af[2][4];
                #pragma unroll
                for (int mt = 0; mt < 2; mt++) {
                    int mb = mt * 16;
                    af[mt][0] = Abh[(mb + g) * ASH + kp0 + tg];
                    af[mt][1] = Abh[(mb + g + 8) * ASH + kp0 + tg];
                    af[mt][2] = Abh[(mb + g) * ASH + kp0 + tg + 4];
                    af[mt][3] = Abh[(mb + g + 8) * ASH + kp0 + tg + 4];
                }
                unsigned bf[2][2];
                #pragma unroll
                for (int nt = 0; nt < 2; nt++) {
                    bf[nt][0] = Wh3h[(kp0 + tg) * WS3H + nt * 8 + g];
                    bf[nt][1] = Wh3h[(kp0 + tg + 4) * WS3H + nt * 8 + g];
                }
                #pragma unroll
                for (int mt = 0; mt < 2; mt++)
                    #pragma unroll
                    for (int nt = 0; nt < 2; nt++)
                        mma_f16(acc[mt][nt], af[mt], bf[nt]);
            }
            #pragma unroll
            for (int mt = 0; mt < 2; mt++)
                #pragma unroll
                for (int nt = 0; nt < 2; nt++) {
                    float* base = &Red[kg * RKG2 + (mt * 16 + g) * RSTR2 + nt * 8 + tg * 2];
                    *(float2*)base = make_float2(acc[mt][nt][0], acc[mt][nt][1]);
                    *(float2*)(base + 8 * RSTR2) = make_float2(acc[mt][nt][2], acc[mt][nt][3]);
                }
        }
        __syncthreads();
        {
            float2 s = *(float2*)&Red[rr2 * RSTR2 + cc2];
            #pragma unroll
            for (int q = 1; q < 8; q++) {
                float2 v = *(float2*)&Red[q * RKG2 + rr2 * RSTR2 + cc2];
                s.x += v.x; s.y += v.y;
            }
            int b = m0 + rr2, n = n02 + cc2;
            float2 gm = h2f2(pf_gm2u);
            float ht0 = tanhf(s.x + pf_pre2.x), ht1 = tanhf(s.y + pf_pre2.y);
            float hd0 = gm.x * pf_h2.x, hd1 = gm.y * pf_h2.y;
            float hn0 = (1.f - pf_z2.x) * hd0 + pf_z2.x * ht0;
            float hn1 = (1.f - pf_z2.y) * hd1 + pf_z2.y * ht1;
            *(float2*)&g_h[b * 512 + n] = make_float2(hn0, hn1);
            *(float2*)&g_hseq[(size_t)(b * Ldim + step) * 512 + n] = make_float2(hn0, hn1);
        }
        groupbar(rg);
    }
}

// ---------------- launch -----------------------------------------------------
extern "C" void kernel_launch(void* const* d_in, const int* in_sizes, int n_in,
                              void* d_out, int out_size) {
    const float* C     = (const float*)d_in[0];
    const float* t     = (const float*)d_in[1];
    const int*   mask  = (const int*)  d_in[2];
    const float* Wx    = (const float*)d_in[3];
    const float* Wh    = (const float*)d_in[4];
    const float* Wm    = (const float*)d_in[5];
    const float* bvec  = (const float*)d_in[6];
    const float* w_gx  = (const float*)d_in[7];
    const float* b_gx  = (const float*)d_in[8];
    const float* W_gh  = (const float*)d_in[9];
    const float* b_gh  = (const float*)d_in[10];
    const float* W_out = (const float*)d_in[11];
    const float* b_out = (const float*)d_in[12];
    float* out = (float*)d_out;

    cudaFuncSetAttribute(k_seq, cudaFuncAttributeMaxDynamicSharedMemorySize, SMEM_SEQ);

    k_xmean<<<Bdim * Hdim / 256, 256>>>(C, mask);
    k_scan <<<Bdim * Hdim / 256, 256>>>(C, t, mask, w_gx, b_gx);
    k_gh_mma <<<dim3(Hdim / 128, BL / 128), 256>>>(W_gh, b_gh);
    k_pre_mma<<<dim3(H3 / 128,  BL / 128), 256>>>(mask, Wx, Wm, bvec);
    k_seq<<<NBLK, 256, SMEM_SEQ>>>(Wh);
    k_out_mma<<<dim3(OUTD / 128, BL / 128), 256>>>(W_out, b_out, out);
}

// round 13
// speedup vs baseline: 1.1767x; 1.1767x over previous
#include <cuda_runtime.h>
#include <cuda_fp16.h>
#include <math.h>

#define Bdim 128
#define Ldim 256
#define Hdim 512
#define H3   1536
#define OUTD 256
#define BL   (Bdim*Ldim)   // 32768
#define NBLK 128

// ---------------- scratch (device globals) ----------------------------------
__device__ float g_xmean[Bdim*Hdim];
__device__ float g_delta[BL*Hdim];
__device__ float g_xhat [BL*Hdim];
__device__ __align__(16) __half g_gammah[BL*Hdim];     // fp16 gamma_h
__device__ float g_pre  [BL*H3];
__device__ float g_hseq [BL*Hdim];
__device__ float g_h    [Bdim*Hdim];
__device__ float g_z    [Bdim*Hdim];
__device__ __align__(16) __half g_rh[Bdim*Hdim];       // fp16 r*gamma*h
__device__ unsigned g_arr4[4*32];
__device__ volatile unsigned g_rel4[4*32];

// ---------------- per-row-group barrier (32 blocks) -------------------------
__device__ __forceinline__ void groupbar(int rg) {
    __syncthreads();
    if (threadIdx.x == 0) {
        __threadfence();
        unsigned gen = g_rel4[rg * 32];
        if (atomicInc((unsigned*)&g_arr4[rg * 32], 31u) == 31u) {
            __threadfence();
            g_rel4[rg * 32] = gen + 1u;
        } else {
            while (g_rel4[rg * 32] == gen) { __nanosleep(4); }
        }
    }
    __syncthreads();
}

__device__ __forceinline__ float sigmoidf_(float x) { return 1.f / (1.f + expf(-x)); }

__device__ __forceinline__ void mma_f16(float* c, const unsigned* a, const unsigned* b) {
    asm volatile("mma.sync.aligned.m16n8k16.row.col.f32.f16.f16.f32 "
        "{%0,%1,%2,%3}, {%4,%5,%6,%7}, {%8,%9}, {%0,%1,%2,%3};"
        : "+f"(c[0]), "+f"(c[1]), "+f"(c[2]), "+f"(c[3])
        : "r"(a[0]), "r"(a[1]), "r"(a[2]), "r"(a[3]), "r"(b[0]), "r"(b[1]));
}
__device__ __forceinline__ unsigned pack_h2(float a, float b) {
    __half2 h = __floats2half2_rn(a, b);
    return *(unsigned*)&h;
}
__device__ __forceinline__ float2 h2f2(unsigned u) {
    __half2 h = *(__half2*)&u;
    return __half22float2(h);
}
__device__ __forceinline__ uint2 pack4(float4 v) {
    return make_uint2(pack_h2(v.x, v.y), pack_h2(v.z, v.w));
}
__device__ __forceinline__ uint4 packB(float4 lo, float4 hi) {
    uint4 r;
    r.x = pack_h2(lo.x, hi.x); r.y = pack_h2(lo.y, hi.y);
    r.z = pack_h2(lo.z, hi.z); r.w = pack_h2(lo.w, hi.w);
    return r;
}

// ---------------- K1: x_mean -------------------------------------------------
__global__ void __launch_bounds__(256) k_xmean(const float* __restrict__ C,
                                               const int* __restrict__ mask) {
    int idx = blockIdx.x * 256 + threadIdx.x;
    int b = idx >> 9, h = idx & 511;
    const int* mp = mask + (size_t)b * Ldim * Hdim + h;
    float s = 0.f, cnt = 0.f;
    #pragma unroll 4
    for (int l = 0; l < Ldim; l++) {
        float m = (float)mp[l * Hdim];
        s   += m * C[l * Hdim + h];
        cnt += m;
    }
    g_xmean[idx] = s / fmaxf(cnt, 1.f);
}

// ---------------- K2: elementwise scans --------------------------------------
__global__ void __launch_bounds__(256) k_scan(const float* __restrict__ C,
                                              const float* __restrict__ t,
                                              const int* __restrict__ mask,
                                              const float* __restrict__ w_gx,
                                              const float* __restrict__ b_gx) {
    int idx = blockIdx.x * 256 + threadIdx.x;
    int b = idx >> 9, h = idx & 511;
    float xm = g_xmean[idx];
    float xl = xm, dprev = 0.f, mprev = 1.f, tprev = 0.f;
    float wg = w_gx[h], bg = b_gx[h];
    const int* mp = mask + (size_t)b * Ldim * Hdim + h;
    const float* tp = t + b * Ldim;
    for (int l = 0; l < Ldim; l++) {
        float tc = tp[l];
        float dt = (l == 0) ? 0.f : (tc - tprev);
        tprev = tc;
        float m = (float)mp[l * Hdim];
        float delta = dt + (1.f - mprev) * dprev;
        float gx = expf(-fmaxf(0.f, wg * delta + bg));
        float x  = C[(l << 9) + h];
        int gi = ((b * Ldim + l) << 9) + h;
        g_delta[gi] = delta;
        g_xhat[gi]  = m * x + (1.f - m) * (gx * xl + (1.f - gx) * xm);
        xl = m * x + (1.f - m) * xl;
        dprev = delta; mprev = m;
    }
}

// =============================================================================
// fp16 m16n8k16 phase-A GEMMs, BK=32, COALESCED A-loads.
// A-loader: warp covers 4 full rows contiguously (4 wavefronts per LDG.128
// instead of 32). ar0 = tid>>3 (+32 per j), ac4 = (tid&7)*4.
// A smem [128][20] half2 words, B smem [16][136].
// =============================================================================
#define ASW 20
#define BSW 136
#define AHW (128*ASW)    // 2560 words
#define BHW (16*BSW)     // 2176 words

#define LOAD_A_F32(src, K, k0)                                                 \
    av0 = *(const float4*)&(src)[(size_t)(bm + ar0)      * (K) + (k0) + ac4];  \
    av1 = *(const float4*)&(src)[(size_t)(bm + ar0 + 32) * (K) + (k0) + ac4];  \
    av2 = *(const float4*)&(src)[(size_t)(bm + ar0 + 64) * (K) + (k0) + ac4];  \
    av3 = *(const float4*)&(src)[(size_t)(bm + ar0 + 96) * (K) + (k0) + ac4];
#define STORE_A(buf)                                                           \
    *(uint2*)&Ah[buf][(ar0)      * ASW + aw2] = pack4(av0);                    \
    *(uint2*)&Ah[buf][(ar0 + 32) * ASW + aw2] = pack4(av1);                    \
    *(uint2*)&Ah[buf][(ar0 + 64) * ASW + aw2] = pack4(av2);                    \
    *(uint2*)&Ah[buf][(ar0 + 96) * ASW + aw2] = pack4(av3);
#define LOAD_B(src, N, k0)                                                     \
    bv0 = *(const float4*)&(src)[(size_t)((k0) + 2 * kpb) * (N) + bn + nc4];   \
    bv1 = *(const float4*)&(src)[(size_t)((k0) + 2 * kpb + 1) * (N) + bn + nc4];\
    bv2 = *(const float4*)&(src)[(size_t)((k0) + 2 * kpb + 16) * (N) + bn + nc4];\
    bv3 = *(const float4*)&(src)[(size_t)((k0) + 2 * kpb + 17) * (N) + bn + nc4];
#define STORE_B(buf)                                                           \
    *(uint4*)&Bh[buf][kpb * BSW + nc4]       = packB(bv0, bv1);                \
    *(uint4*)&Bh[buf][(kpb + 8) * BSW + nc4] = packB(bv2, bv3);

#define MMA_STAGE(buf)                                                         \
    {                                                                          \
        const unsigned* A = Ah[buf];                                           \
        const unsigned* B = Bh[buf];                                           \
        _Pragma("unroll")                                                      \
        for (int s = 0; s < 2; s++) {                                          \
            unsigned af[4][4], bf[4][2];                                       \
            _Pragma("unroll")                                                  \
            for (int mt = 0; mt < 4; mt++) {                                   \
                int mb = wm + mt * 16;                                         \
                af[mt][0] = A[(mb + g) * ASW + s * 8 + tg];                    \
                af[mt][1] = A[(mb + g + 8) * ASW + s * 8 + tg];                \
                af[mt][2] = A[(mb + g) * ASW + s * 8 + tg + 4];                \
                af[mt][3] = A[(mb + g + 8) * ASW + s * 8 + tg + 4];            \
            }                                                                  \
            _Pragma("unroll")                                                  \
            for (int nt = 0; nt < 4; nt++) {                                   \
                int nb = wn + nt * 8;                                          \
                bf[nt][0] = B[(s * 8 + tg) * BSW + nb + g];                    \
                bf[nt][1] = B[(s * 8 + tg + 4) * BSW + nb + g];                \
            }                                                                  \
            _Pragma("unroll")                                                  \
            for (int mt = 0; mt < 4; mt++)                                     \
                _Pragma("unroll")                                              \
                for (int nt = 0; nt < 4; nt++)                                 \
                    mma_f16(acc[mt][nt], af[mt], bf[nt]);                      \
        }                                                                      \
    }

#define GEMM_DECLS                                                             \
    const int tid = threadIdx.x;                                               \
    const int bn = blockIdx.x * 128, bm = blockIdx.y * 128;                    \
    const int wid = tid >> 5, lane = tid & 31;                                 \
    const int wm = (wid >> 2) * 64, wn = (wid & 3) * 32;                       \
    const int g = lane >> 2, tg = lane & 3;                                    \
    const int ar0 = tid >> 3, ac4 = (tid & 7) * 4, aw2 = (tid & 7) * 2;        \
    const int kpb = tid >> 5, nc4 = lane * 4;                                  \
    float acc[4][4][4];                                                        \
    _Pragma("unroll")                                                          \
    for (int i = 0; i < 4; i++)                                                \
        _Pragma("unroll")                                                      \
        for (int j = 0; j < 4; j++)                                            \
            _Pragma("unroll")                                                  \
            for (int q = 0; q < 4; q++) acc[i][j][q] = 0.f;                    \
    float4 av0, av1, av2, av3, bv0, bv1, bv2, bv3;

// ---------------- K3: gamma_h = exp(-relu(delta @ W_gh + b_gh)) -> fp16 ------
__global__ void __launch_bounds__(256, 2) k_gh_mma(const float* __restrict__ Bw,
                                                   const float* __restrict__ bias) {
    __shared__ __align__(16) unsigned Ah[2][AHW];
    __shared__ __align__(16) unsigned Bh[2][BHW];
    GEMM_DECLS
    LOAD_A_F32(g_delta, Hdim, 0) LOAD_B(Bw, Hdim, 0)
    STORE_A(0) STORE_B(0)
    __syncthreads();
    const int KT = Hdim / 32;   // 16
    for (int kt = 0; kt < KT; kt++) {
        if (kt + 1 < KT) {
            int k0 = (kt + 1) * 32;
            LOAD_A_F32(g_delta, Hdim, k0) LOAD_B(Bw, Hdim, k0)
        }
        MMA_STAGE(kt & 1)
        if (kt + 1 < KT) { STORE_A((kt + 1) & 1) STORE_B((kt + 1) & 1) }
        __syncthreads();
    }
    #pragma unroll
    for (int mt = 0; mt < 4; mt++) {
        #pragma unroll
        for (int nt = 0; nt < 4; nt++) {
            int col = bn + wn + nt * 8 + tg * 2;
            float b0 = bias[col], b1 = bias[col + 1];
            int r0 = bm + wm + mt * 16 + g;
            float e00 = expf(-fmaxf(0.f, acc[mt][nt][0] + b0));
            float e01 = expf(-fmaxf(0.f, acc[mt][nt][1] + b1));
            float e10 = expf(-fmaxf(0.f, acc[mt][nt][2] + b0));
            float e11 = expf(-fmaxf(0.f, acc[mt][nt][3] + b1));
            *(unsigned*)&g_gammah[(size_t)r0 * Hdim + col] = pack_h2(e00, e01);
            *(unsigned*)&g_gammah[(size_t)(r0 + 8) * Hdim + col] = pack_h2(e10, e11);
        }
    }
}

// ---------------- K4: pre = x_hat@Wx + m@Wm + b (K virtualized 1024) ---------
__global__ void __launch_bounds__(256, 2) k_pre_mma(const int* __restrict__ mask,
                                                    const float* __restrict__ Wx,
                                                    const float* __restrict__ Wm,
                                                    const float* __restrict__ bias) {
    __shared__ __align__(16) unsigned Ah[2][AHW];
    __shared__ __align__(16) unsigned Bh[2][BHW];
    GEMM_DECLS
    LOAD_A_F32(g_xhat, Hdim, 0) LOAD_B(Wx, H3, 0)
    STORE_A(0) STORE_B(0)
    __syncthreads();
    const int KT = 32;   // 2 passes x 16
    for (int kt = 0; kt < KT; kt++) {
        if (kt + 1 < KT) {
            int nkt = kt + 1;
            int k0 = (nkt & 15) * 32;
            if (nkt < 16) {
                LOAD_A_F32(g_xhat, Hdim, k0) LOAD_B(Wx, H3, k0)
            } else {
                int4 m0 = *(const int4*)&mask[(size_t)(bm + ar0)      * Hdim + k0 + ac4];
                int4 m1 = *(const int4*)&mask[(size_t)(bm + ar0 + 32) * Hdim + k0 + ac4];
                int4 m2 = *(const int4*)&mask[(size_t)(bm + ar0 + 64) * Hdim + k0 + ac4];
                int4 m3 = *(const int4*)&mask[(size_t)(bm + ar0 + 96) * Hdim + k0 + ac4];
                av0 = make_float4((float)m0.x, (float)m0.y, (float)m0.z, (float)m0.w);
                av1 = make_float4((float)m1.x, (float)m1.y, (float)m1.z, (float)m1.w);
                av2 = make_float4((float)m2.x, (float)m2.y, (float)m2.z, (float)m2.w);
                av3 = make_float4((float)m3.x, (float)m3.y, (float)m3.z, (float)m3.w);
                LOAD_B(Wm, H3, k0)
            }
        }
        MMA_STAGE(kt & 1)
        if (kt + 1 < KT) { STORE_A((kt + 1) & 1) STORE_B((kt + 1) & 1) }
        __syncthreads();
    }
    #pragma unroll
    for (int mt = 0; mt < 4; mt++) {
        #pragma unroll
        for (int nt = 0; nt < 4; nt++) {
            int col = bn + wn + nt * 8 + tg * 2;
            float b0 = bias[col], b1 = bias[col + 1];
            int r0 = bm + wm + mt * 16 + g;
            float2 o0, o1;
            o0.x = acc[mt][nt][0] + b0; o0.y = acc[mt][nt][1] + b1;
            o1.x = acc[mt][nt][2] + b0; o1.y = acc[mt][nt][3] + b1;
            *(float2*)&g_pre[(size_t)r0 * H3 + col] = o0;
            *(float2*)&g_pre[(size_t)(r0 + 8) * H3 + col] = o1;
        }
    }
}

// ---------------- K6: out = h_seq @ W_out + b_out ----------------------------
__global__ void __launch_bounds__(256, 2) k_out_mma(const float* __restrict__ Bw,
                                                    const float* __restrict__ bias,
                                                    float* __restrict__ out) {
    __shared__ __align__(16) unsigned Ah[2][AHW];
    __shared__ __align__(16) unsigned Bh[2][BHW];
    GEMM_DECLS
    LOAD_A_F32(g_hseq, Hdim, 0) LOAD_B(Bw, OUTD, 0)
    STORE_A(0) STORE_B(0)
    __syncthreads();
    const int KT = Hdim / 32;
    for (int kt = 0; kt < KT; kt++) {
        if (kt + 1 < KT) {
            int k0 = (kt + 1) * 32;
            LOAD_A_F32(g_hseq, Hdim, k0) LOAD_B(Bw, OUTD, k0)
        }
        MMA_STAGE(kt & 1)
        if (kt + 1 < KT) { STORE_A((kt + 1) & 1) STORE_B((kt + 1) & 1) }
        __syncthreads();
    }
    #pragma unroll
    for (int mt = 0; mt < 4; mt++) {
        #pragma unroll
        for (int nt = 0; nt < 4; nt++) {
            int col = bn + wn + nt * 8 + tg * 2;
            float b0 = bias[col], b1 = bias[col + 1];
            int r0 = bm + wm + mt * 16 + g;
            float2 o0, o1;
            o0.x = acc[mt][nt][0] + b0; o0.y = acc[mt][nt][1] + b1;
            o1.x = acc[mt][nt][2] + b0; o1.y = acc[mt][nt][3] + b1;
            *(float2*)&out[(size_t)r0 * OUTD + col] = o0;
            *(float2*)&out[(size_t)(r0 + 8) * OUTD + col] = o1;
        }
    }
}

// =============================================================================
// K5: persistent sequential recurrence — unchanged from R10 (fp16 data plane).
// =============================================================================
#define OFF_WH1 0
#define WS1H    40
#define OFF_WH3 10240
#define WS3H    24
#define OFF_AB  16384
#define ASH     260
#define OFF_RED 24704
#define RSTR1   36
#define RKG1    (32*RSTR1)
#define RSTR2   20
#define RKG2    (32*RSTR2)
#define SMEM_SEQ ((OFF_RED + 8*RKG1) * 4)   // 135680 B

__global__ void __launch_bounds__(256, 1) k_seq(const float* __restrict__ Wh) {
    extern __shared__ unsigned smu[];
    unsigned* Wh1h = smu + OFF_WH1;
    unsigned* Wh3h = smu + OFF_WH3;
    unsigned* Abh  = smu + OFF_AB;
    float*    Red  = (float*)(smu + OFF_RED);

    const int tid = threadIdx.x;
    const int blk = blockIdx.x;
    const int rg  = blk >> 5;
    const int tn  = blk & 31;
    const int m0  = rg * 32;
    const int n0  = tn * 32;
    const int n02 = tn * 16;

    for (int i = tid; i < 256 * 32; i += 256) {
        int kp = i >> 5, n = i & 31;
        float lo = Wh[(size_t)(2 * kp) * H3 + n0 + n];
        float hi = Wh[(size_t)(2 * kp + 1) * H3 + n0 + n];
        Wh1h[kp * WS1H + n] = pack_h2(lo, hi);
    }
    for (int i = tid; i < 256 * 16; i += 256) {
        int kp = i >> 4, n = i & 15;
        float lo = Wh[(size_t)(2 * kp) * H3 + 1024 + n02 + n];
        float hi = Wh[(size_t)(2 * kp + 1) * H3 + 1024 + n02 + n];
        Wh3h[kp * WS3H + n] = pack_h2(lo, hi);
    }
    if (tn == 0)
        for (int i = tid; i < 32 * 512; i += 256) g_h[m0 * 512 + i] = 0.f;
    groupbar(rg);

    const int lane = tid & 31, kg = tid >> 5;
    const int g = lane >> 2, tg = lane & 3;
    const int kpbase = (kg * 64) >> 1;
    const int pr = tid >> 3, pc = (tid & 7) * 4;
    const int pw = (tid & 7) * 4;
    const int rr1 = tid >> 3, cc1 = (tid * 4) & 31;
    const int rr2 = tid >> 3, cc2 = (tid * 2) & 15;
    const int nn1 = (n0 >= 512 ? n0 - 512 : 0) + cc1;

    for (int step = 0; step < Ldim; step++) {
        float4 pf_pre4 = __ldcg((const float4*)&g_pre[(size_t)((m0 + rr1) * Ldim + step) * H3 + n0 + cc1]);
        float2 pf_pre2 = __ldcg((const float2*)&g_pre[(size_t)((m0 + rr2) * Ldim + step) * H3 + 1024 + n02 + cc2]);
        unsigned pf_gm2u = *(const unsigned*)&g_gammah[(size_t)((m0 + rr2) * Ldim + step) * 512 + n02 + cc2];
        float2 pf_h2   = __ldcg((const float2*)&g_h[(m0 + rr2) * 512 + n02 + cc2]);
        uint2  pf_gm1u = *(const uint2*)&g_gammah[(size_t)((m0 + rr1) * Ldim + step) * 512 + nn1];
        float4 pf_h1   = __ldcg((const float4*)&g_h[(m0 + rr1) * 512 + nn1]);

        {
            const float* hrow = g_h + (m0 + pr) * 512;
            const __half* grow = g_gammah + (size_t)((m0 + pr) * Ldim + step) * 512;
            #pragma unroll
            for (int j = 0; j < 16; j++) {
                int k = pc + 32 * j;
                float4 h4 = __ldcg((const float4*)(hrow + k));
                uint2 gp = *(const uint2*)(grow + k);
                float2 f01 = h2f2(gp.x), f23 = h2f2(gp.y);
                unsigned o0 = pack_h2(h4.x * f01.x, h4.y * f01.y);
                unsigned o1 = pack_h2(h4.z * f23.x, h4.w * f23.y);
                *(uint2*)&Abh[pr * ASH + (k >> 1)] = make_uint2(o0, o1);
            }
        }
        __syncthreads();
        {
            float acc[2][4][4];
            #pragma unroll
            for (int mt = 0; mt < 2; mt++)
                #pragma unroll
                for (int nt = 0; nt < 4; nt++)
                    #pragma unroll
                    for (int q = 0; q < 4; q++) acc[mt][nt][q] = 0.f;
            #pragma unroll
            for (int ks = 0; ks < 4; ks++) {
                int kp0 = kpbase + ks * 8;
                unsigned af[2][4];
                #pragma unroll
                for (int mt = 0; mt < 2; mt++) {
                    int mb = mt * 16;
                    af[mt][0] = Abh[(mb + g) * ASH + kp0 + tg];
                    af[mt][1] = Abh[(mb + g + 8) * ASH + kp0 + tg];
                    af[mt][2] = Abh[(mb + g) * ASH + kp0 + tg + 4];
                    af[mt][3] = Abh[(mb + g + 8) * ASH + kp0 + tg + 4];
                }
                unsigned bf[4][2];
                #pragma unroll
                for (int nt = 0; nt < 4; nt++) {
                    bf[nt][0] = Wh1h[(kp0 + tg) * WS1H + nt * 8 + g];
                    bf[nt][1] = Wh1h[(kp0 + tg + 4) * WS1H + nt * 8 + g];
                }
                #pragma unroll
                for (int mt = 0; mt < 2; mt++)
                    #pragma unroll
                    for (int nt = 0; nt < 4; nt++)
                        mma_f16(acc[mt][nt], af[mt], bf[nt]);
            }
            #pragma unroll
            for (int mt = 0; mt < 2; mt++)
                #pragma unroll
                for (int nt = 0; nt < 4; nt++) {
                    float* base = &Red[kg * RKG1 + (mt * 16 + g) * RSTR1 + nt * 8 + tg * 2];
                    *(float2*)base = make_float2(acc[mt][nt][0], acc[mt][nt][1]);
                    *(float2*)(base + 8 * RSTR1) = make_float2(acc[mt][nt][2], acc[mt][nt][3]);
                }
        }
        __syncthreads();
        {
            float4 s = *(float4*)&Red[rr1 * RSTR1 + cc1];
            #pragma unroll
            for (int q = 1; q < 8; q++) {
                float4 v = *(float4*)&Red[q * RKG1 + rr1 * RSTR1 + cc1];
                s.x += v.x; s.y += v.y; s.z += v.z; s.w += v.w;
            }
            int b = m0 + rr1;
            float s0 = sigmoidf_(s.x + pf_pre4.x);
            float s1 = sigmoidf_(s.y + pf_pre4.y);
            float s2 = sigmoidf_(s.z + pf_pre4.z);
            float s3 = sigmoidf_(s.w + pf_pre4.w);
            if (n0 < 512) {
                *(float4*)&g_z[b * 512 + n0 + cc1] = make_float4(s0, s1, s2, s3);
            } else {
                float2 ga = h2f2(pf_gm1u.x), gb = h2f2(pf_gm1u.y);
                unsigned r01 = pack_h2(s0 * ga.x * pf_h1.x, s1 * ga.y * pf_h1.y);
                unsigned r23 = pack_h2(s2 * gb.x * pf_h1.z, s3 * gb.y * pf_h1.w);
                *(uint2*)&g_rh[b * 512 + nn1] = make_uint2(r01, r23);
            }
        }
        groupbar(rg);

        float2 pf_z2 = __ldcg((const float2*)&g_z[(m0 + rr2) * 512 + n02 + cc2]);

        {
            const unsigned* rrow = (const unsigned*)(g_rh + (m0 + pr) * 512);
            #pragma unroll
            for (int j = 0; j < 8; j++) {
                int w = pw + 32 * j;
                *(uint4*)&Abh[pr * ASH + w] = __ldcg((const uint4*)(rrow + w));
            }
        }
        __syncthreads();
        {
            float acc[2][2][4];
            #pragma unroll
            for (int mt = 0; mt < 2; mt++)
                #pragma unroll
                for (int nt = 0; nt < 2; nt++)
                    #pragma unroll
                    for (int q = 0; q < 4; q++) acc[mt][nt][q] = 0.f;
            #pragma unroll
            for (int ks = 0; ks < 4; ks++) {
                int kp0 = kpbase + ks * 8;
                unsigned af[2][4];
                #pragma unroll
                for (int mt = 0; mt < 2; mt++) {
                    int mb = mt * 16;
                    af[mt][0] = Abh[(mb + g) * ASH + kp0 + tg];
                    af[mt][1] = Abh[(mb + g + 8) * ASH + kp0 + tg];
                    af[mt][2] = Abh[(mb + g) * ASH + kp0 + tg + 4];
                    af[mt][3] = Abh[(mb + g + 8) * ASH + kp0 + tg + 4];
                }
                unsigned bf[2][2];
                #pragma unroll
                for (int nt = 0; nt < 2; nt++) {
                    bf[nt][0] = Wh3h[(kp0 + tg) * WS3H + nt * 8 + g];
                    bf[nt][1] = Wh3h[(kp0 + tg + 4) * WS3H + nt * 8 + g];
                }
                #pragma unroll
                for (int mt = 0; mt < 2; mt++)
                    #pragma unroll
                    for (int nt = 0; nt < 2; nt++)
                        mma_f16(acc[mt][nt], af[mt], bf[nt]);
            }
            #pragma unroll
            for (int mt = 0; mt < 2; mt++)
                #pragma unroll
                for (int nt = 0; nt < 2; nt++) {
                    float* base = &Red[kg * RKG2 + (mt * 16 + g) * RSTR2 + nt * 8 + tg * 2];
                    *(float2*)base = make_float2(acc[mt][nt][0], acc[mt][nt][1]);
                    *(float2*)(base + 8 * RSTR2) = make_float2(acc[mt][nt][2], acc[mt][nt][3]);
                }
        }
        __syncthreads();
        {
            float2 s = *(float2*)&Red[rr2 * RSTR2 + cc2];
            #pragma unroll
            for (int q = 1; q < 8; q++) {
                float2 v = *(float2*)&Red[q * RKG2 + rr2 * RSTR2 + cc2];
                s.x += v.x; s.y += v.y;
            }
            int b = m0 + rr2, n = n02 + cc2;
            float2 gm = h2f2(pf_gm2u);
            float ht0 = tanhf(s.x + pf_pre2.x), ht1 = tanhf(s.y + pf_pre2.y);
            float hd0 = gm.x * pf_h2.x, hd1 = gm.y * pf_h2.y;
            float hn0 = (1.f - pf_z2.x) * hd0 + pf_z2.x * ht0;
            float hn1 = (1.f - pf_z2.y) * hd1 + pf_z2.y * ht1;
            *(float2*)&g_h[b * 512 + n] = make_float2(hn0, hn1);
            *(float2*)&g_hseq[(size_t)(b * Ldim + step) * 512 + n] = make_float2(hn0, hn1);
        }
        groupbar(rg);
    }
}

// ---------------- launch -----------------------------------------------------
extern "C" void kernel_launch(void* const* d_in, const int* in_sizes, int n_in,
                              void* d_out, int out_size) {
    const float* C     = (const float*)d_in[0];
    const float* t     = (const float*)d_in[1];
    const int*   mask  = (const int*)  d_in[2];
    const float* Wx    = (const float*)d_in[3];
    const float* Wh    = (const float*)d_in[4];
    const float* Wm    = (const float*)d_in[5];
    const float* bvec  = (const float*)d_in[6];
    const float* w_gx  = (const float*)d_in[7];
    const float* b_gx  = (const float*)d_in[8];
    const float* W_gh  = (const float*)d_in[9];
    const float* b_gh  = (const float*)d_in[10];
    const float* W_out = (const float*)d_in[11];
    const float* b_out = (const float*)d_in[12];
    float* out = (float*)d_out;

    cudaFuncSetAttribute(k_seq, cudaFuncAttributeMaxDynamicSharedMemorySize, SMEM_SEQ);

    k_xmean<<<Bdim * Hdim / 256, 256>>>(C, mask);
    k_scan <<<Bdim * Hdim / 256, 256>>>(C, t, mask, w_gx, b_gx);
    k_gh_mma <<<dim3(Hdim / 128, BL / 128), 256>>>(W_gh, b_gh);
    k_pre_mma<<<dim3(H3 / 128,  BL / 128), 256>>>(mask, Wx, Wm, bvec);
    k_seq<<<NBLK, 256, SMEM_SEQ>>>(Wh);
    k_out_mma<<<dim3(OUTD / 128, BL / 128), 256>>>(W_out, b_out, out);
}